// round 5
// baseline (speedup 1.0000x reference)
#include <cuda_runtime.h>
#include <cuda_bf16.h>
#include <cstdint>

// Problem constants
#define Bb 8
#define Nn 1024
#define Cc 768
#define Hh 12
#define Dd 64

typedef __nv_bfloat16 bf16;

// ---------------- scratch (__device__ globals; allocation-free) ----------------
__device__ float g_qkv[(size_t)Bb * Nn * 3 * Cc];      // fp32 qkv
__device__ float g_av [(size_t)Bb * Nn * Cc];          // fp32 A@V

__device__ bf16 g_xh[(size_t)Bb * Nn * Cc], g_xl[(size_t)Bb * Nn * Cc];
__device__ bf16 g_wqh[(size_t)3 * Cc * Cc], g_wql[(size_t)3 * Cc * Cc];
__device__ bf16 g_wph[(size_t)Cc * Cc],     g_wpl[(size_t)Cc * Cc];
__device__ bf16 g_qh [(size_t)Bb * Hh * Nn * Dd], g_ql [(size_t)Bb * Hh * Nn * Dd];
__device__ bf16 g_kh [(size_t)Bb * Hh * Nn * Dd], g_kl [(size_t)Bb * Hh * Nn * Dd];
__device__ bf16 g_vth[(size_t)Bb * Hh * Dd * Nn], g_vtl[(size_t)Bb * Hh * Dd * Nn];
__device__ bf16 g_sah[(size_t)Hh * Nn * Nn], g_sal[(size_t)Hh * Nn * Nn];
__device__ bf16 g_th [(size_t)Bb * Nn * Cc], g_tl [(size_t)Bb * Nn * Cc];

// ---------------- helpers ----------------
__device__ __forceinline__ uint32_t smem_u32(const void* p) {
    uint32_t a;
    asm("{ .reg .u64 t; cvta.to.shared.u64 t, %1; cvt.u32.u64 %0, t; }" : "=r"(a) : "l"(p));
    return a;
}
__device__ __forceinline__ void cpasync16(uint32_t dst, const void* src) {
    asm volatile("cp.async.cg.shared.global [%0], [%1], 16;" :: "r"(dst), "l"(src));
}
#define CP_COMMIT() asm volatile("cp.async.commit_group;" ::: "memory")
#define CP_WAIT1()  asm volatile("cp.async.wait_group 1;" ::: "memory")
#define CP_WAIT0()  asm volatile("cp.async.wait_group 0;" ::: "memory")

#define LDX4(r, a)                                                               \
    asm volatile("ldmatrix.sync.aligned.m8n8.x4.shared.b16 {%0,%1,%2,%3}, [%4];" \
        : "=r"((r)[0]), "=r"((r)[1]), "=r"((r)[2]), "=r"((r)[3]) : "r"(a))

__device__ __forceinline__ void mma_bf(float* c, const uint32_t* a, const uint32_t* b) {
    asm volatile(
        "mma.sync.aligned.m16n8k16.row.col.f32.bf16.bf16.f32 "
        "{%0,%1,%2,%3}, {%4,%5,%6,%7}, {%8,%9}, {%0,%1,%2,%3};"
        : "+f"(c[0]), "+f"(c[1]), "+f"(c[2]), "+f"(c[3])
        : "r"(a[0]), "r"(a[1]), "r"(a[2]), "r"(a[3]), "r"(b[0]), "r"(b[1]));
}

__device__ __forceinline__ void split_f(float v, bf16& h, bf16& l) {
    h = __float2bfloat16(v);
    l = __float2bfloat16(v - __bfloat162float(h));
}
__device__ __forceinline__ uint32_t pack2(bf16 a, bf16 b) {
    __nv_bfloat162 t(a, b);
    return *reinterpret_cast<uint32_t*>(&t);
}

// ---------------- dense MMA GEMM: BM=128, BN=64, BK=32, 256 thr, 3 CTA/SM ----------------
__device__ __forceinline__ void load_stage64(
    uint32_t sb, int tid, int row0, int col0, int k0,
    const bf16* __restrict__ Ah, const bf16* __restrict__ Al, int lda,
    const bf16* __restrict__ Bh, const bf16* __restrict__ Bl, int ldb)
{
#pragma unroll
    for (int v = 0; v < 2; v++) {
        int idx = tid + v * 256;            // 512: 128 rows x 4 chunks
        int r = idx >> 2, ch = idx & 3;
        long go = (long)(row0 + r) * lda + k0 + ch * 8;
        uint32_t d = sb + r * 80 + ch * 16;
        cpasync16(d,         Ah + go);
        cpasync16(d + 10240, Al + go);
    }
    {
        int r = tid >> 2, ch = tid & 3;     // 256: 64 rows x 4 chunks
        long go = (long)(col0 + r) * ldb + k0 + ch * 8;
        uint32_t d = sb + 20480 + r * 80 + ch * 16;
        cpasync16(d,        Bh + go);
        cpasync16(d + 5120, Bl + go);
    }
}

#define G_STG 30720   // 20480 (A hi/lo) + 2*5120 (B hi/lo)

__global__ __launch_bounds__(256, 3) void gemm_mma(
    const bf16* __restrict__ Ah, const bf16* __restrict__ Al, int lda, long sAo, long sAi,
    const bf16* __restrict__ Bh, const bf16* __restrict__ Bl, int ldb, long sBo, long sBi,
    float* __restrict__ C, int ldc, long sCo, long sCi,
    int K, const float* __restrict__ bias, float scale, int hdiv)
{
    extern __shared__ char smem[];
    const uint32_t sbase = smem_u32(smem);

    const int tid = threadIdx.x;
    const int wid = tid >> 5, lane = tid & 31;
    const int wr = wid >> 2, wc = wid & 3;
    const int wm0 = wr * 64;
    const int wn0 = wc * 16;

    const int z = blockIdx.z;
    const int zo = z / hdiv, zi = z - zo * hdiv;
    Ah += (long)zo * sAo + (long)zi * sAi;
    Al += (long)zo * sAo + (long)zi * sAi;
    Bh += (long)zo * sBo + (long)zi * sBi;
    Bl += (long)zo * sBo + (long)zi * sBi;
    const long cofs = (long)zo * sCo + (long)zi * sCi;

    const int row0 = blockIdx.y * 128;
    const int col0 = blockIdx.x * 64;

    const int lrA = (lane & 7) + ((lane >> 3) & 1) * 8;
    const int cA  = lane >> 4;
    const int lrB = (lane & 7) + (lane >> 4) * 8;
    const int cB  = (lane >> 3) & 1;

    float acc[4][2][4];
#pragma unroll
    for (int mi = 0; mi < 4; mi++)
#pragma unroll
        for (int ni = 0; ni < 2; ni++)
#pragma unroll
            for (int e = 0; e < 4; e++) acc[mi][ni][e] = 0.f;

    const int niter = K >> 5;
    load_stage64(sbase, tid, row0, col0, 0, Ah, Al, lda, Bh, Bl, ldb);
    CP_COMMIT();

    for (int c = 0; c < niter; c++) {
        if (c + 1 < niter) {
            load_stage64(sbase + ((c + 1) & 1) * G_STG, tid, row0, col0, (c + 1) * 32,
                         Ah, Al, lda, Bh, Bl, ldb);
            CP_COMMIT();
            CP_WAIT1();
        } else {
            CP_WAIT0();
        }
        __syncthreads();

        const uint32_t sb = sbase + (c & 1) * G_STG;
#pragma unroll
        for (int kk = 0; kk < 2; kk++) {
            uint32_t bhf[2][2], blf[2][2];
            {
                uint32_t off = (uint32_t)((wn0 + lrB) * 80 + (kk * 2 + cB) * 16);
                uint32_t t[4];
                LDX4(t, sb + 20480 + off);
                bhf[0][0] = t[0]; bhf[0][1] = t[1];
                bhf[1][0] = t[2]; bhf[1][1] = t[3];
                LDX4(t, sb + 25600 + off);
                blf[0][0] = t[0]; blf[0][1] = t[1];
                blf[1][0] = t[2]; blf[1][1] = t[3];
            }
#pragma unroll
            for (int mi = 0; mi < 4; mi++) {
                uint32_t ah[4], al[4];
                uint32_t off = (uint32_t)((wm0 + mi * 16 + lrA) * 80 + (kk * 2 + cA) * 16);
                LDX4(ah, sb + off);
                LDX4(al, sb + 10240 + off);
#pragma unroll
                for (int ni = 0; ni < 2; ni++) {
                    mma_bf(acc[mi][ni], ah, bhf[ni]);
                    mma_bf(acc[mi][ni], ah, blf[ni]);
                    mma_bf(acc[mi][ni], al, bhf[ni]);
                }
            }
        }
        __syncthreads();
    }

#pragma unroll
    for (int ni = 0; ni < 2; ni++) {
        const int col = col0 + wn0 + ni * 8 + (lane & 3) * 2;
        float b0 = 0.f, b1 = 0.f;
        if (bias) { b0 = bias[col]; b1 = bias[col + 1]; }
#pragma unroll
        for (int mi = 0; mi < 4; mi++) {
            const int r = row0 + wm0 + mi * 16 + (lane >> 2);
            const long off0 = cofs + (long)r * ldc + col;
            const long off1 = off0 + (long)8 * ldc;
            float2 p0 = { acc[mi][ni][0] * scale + b0, acc[mi][ni][1] * scale + b1 };
            float2 p1 = { acc[mi][ni][2] * scale + b0, acc[mi][ni][3] * scale + b1 };
            *(float2*)(C + off0) = p0;
            *(float2*)(C + off1) = p1;
        }
    }
}

// ---------------- flash attention: O = softmax(Q K^T) V  (+ g_av) ----------------
// ktile=64, 2-stage, smem 110592 -> 2 CTA/SM. Q pre-scaled by 0.125.
#define FQ_PITCH 144
#define F_QL   18432
#define F_S0   36864
#define FS_KL  9216
#define FS_VH  18432
#define F_STG  36864
#define F_SMEM (36864 + 2 * 36864)

__device__ __forceinline__ void flash_load_kv(
    uint32_t dst, int tid, int kt,
    const bf16* __restrict__ Kh, const bf16* __restrict__ Kl,
    const bf16* __restrict__ Vth, const bf16* __restrict__ Vtl)
{
#pragma unroll
    for (int v = 0; v < 2; v++) {
        int idx = tid + v * 256;             // 512: 64 rows x 8 chunks
        int r = idx >> 3, ch = idx & 7;
        uint32_t d = dst + r * FQ_PITCH + ch * 16;
        long src = (long)(kt * 64 + r) * 64 + ch * 8;
        cpasync16(d,         Kh + src);
        cpasync16(d + FS_KL, Kl + src);
    }
#pragma unroll
    for (int v = 0; v < 2; v++) {
        int idx = tid + v * 256;             // 512: 64 d-rows x 8 chunks
        int r = idx >> 3, ch = idx & 7;
        uint32_t d = dst + FS_VH + r * FQ_PITCH + ch * 16;
        long src = (long)r * Nn + kt * 64 + ch * 8;
        cpasync16(d,         Vth + src);
        cpasync16(d + FS_KL, Vtl + src);
    }
}

__global__ __launch_bounds__(256) void flash_kernel(
    const bf16* __restrict__ qh_, const bf16* __restrict__ ql_,
    const bf16* __restrict__ kh_, const bf16* __restrict__ kl_,
    const bf16* __restrict__ vth_, const bf16* __restrict__ vtl_,
    const float* __restrict__ av_,
    bf16* __restrict__ th_, bf16* __restrict__ tl_)
{
    extern __shared__ char smem[];
    const uint32_t sb = smem_u32(smem);
    const int tid = threadIdx.x, wid = tid >> 5, lane = tid & 31;
    const int qt = blockIdx.x, bh = blockIdx.y;
    const int b = bh / Hh, h = bh - b * Hh;

    const bf16* Qh  = qh_  + (long)bh * Nn * Dd + (long)qt * 128 * Dd;
    const bf16* Ql  = ql_  + (long)bh * Nn * Dd + (long)qt * 128 * Dd;
    const bf16* Kh  = kh_  + (long)bh * Nn * Dd;
    const bf16* Kl  = kl_  + (long)bh * Nn * Dd;
    const bf16* Vth = vth_ + (long)bh * Dd * Nn;
    const bf16* Vtl = vtl_ + (long)bh * Dd * Nn;

    const int lrA = (lane & 7) + ((lane >> 3) & 1) * 8;
    const int cA  = lane >> 4;
    const int lrB = (lane & 7) + (lane >> 4) * 8;
    const int cB  = (lane >> 3) & 1;

    // prologue: Q (128 rows x 64) + stage 0
#pragma unroll
    for (int v = 0; v < 4; v++) {
        int idx = tid + v * 256;
        int r = idx >> 3, ch = idx & 7;
        uint32_t d = sb + r * FQ_PITCH + ch * 16;
        long src = (long)r * 64 + ch * 8;
        cpasync16(d,        Qh + src);
        cpasync16(d + F_QL, Ql + src);
    }
    flash_load_kv(sb + F_S0, tid, 0, Kh, Kl, Vth, Vtl);
    CP_COMMIT();

    uint32_t qfh[4][4], qfl[4][4];
    float o[8][4];
#pragma unroll
    for (int ni = 0; ni < 8; ni++)
#pragma unroll
        for (int e = 0; e < 4; e++) o[ni][e] = 0.f;
    float m0 = -1e30f, m1 = -1e30f, l0 = 0.f, l1 = 0.f;

    for (int kt = 0; kt < 16; kt++) {
        if (kt + 1 < 16) {
            flash_load_kv(sb + F_S0 + ((kt + 1) & 1) * F_STG, tid, kt + 1, Kh, Kl, Vth, Vtl);
            CP_COMMIT();
            CP_WAIT1();
        } else {
            CP_WAIT0();
        }
        __syncthreads();

        if (kt == 0) {
#pragma unroll
            for (int kc = 0; kc < 4; kc++) {
                uint32_t off = (uint32_t)((wid * 16 + lrA) * FQ_PITCH + (kc * 2 + cA) * 16);
                LDX4(qfh[kc], sb + off);
                LDX4(qfl[kc], sb + F_QL + off);
            }
        }

        const uint32_t sK = sb + F_S0 + (kt & 1) * F_STG;
        const uint32_t sV = sK + FS_VH;

        // ---- S = Q K^T  (m16 x n64) ----
        float s[8][4];
#pragma unroll
        for (int j = 0; j < 8; j++)
#pragma unroll
            for (int e = 0; e < 4; e++) s[j][e] = 0.f;
#pragma unroll
        for (int p = 0; p < 4; p++) {
#pragma unroll
            for (int kc = 0; kc < 4; kc++) {
                uint32_t off = (uint32_t)((p * 16 + lrB) * FQ_PITCH + (kc * 2 + cB) * 16);
                uint32_t tb[4], tl4[4];
                LDX4(tb, sK + off);
                LDX4(tl4, sK + FS_KL + off);
                uint32_t b0h[2] = { tb[0], tb[1] }, b1h[2] = { tb[2], tb[3] };
                uint32_t b0l[2] = { tl4[0], tl4[1] }, b1l[2] = { tl4[2], tl4[3] };
                mma_bf(s[2 * p],     qfh[kc], b0h);
                mma_bf(s[2 * p],     qfh[kc], b0l);
                mma_bf(s[2 * p],     qfl[kc], b0h);
                mma_bf(s[2 * p + 1], qfh[kc], b1h);
                mma_bf(s[2 * p + 1], qfh[kc], b1l);
                mma_bf(s[2 * p + 1], qfl[kc], b1h);
            }
        }

        // ---- online softmax stats ----
        float mx0 = -1e30f, mx1 = -1e30f;
#pragma unroll
        for (int j = 0; j < 8; j++) {
            mx0 = fmaxf(mx0, fmaxf(s[j][0], s[j][1]));
            mx1 = fmaxf(mx1, fmaxf(s[j][2], s[j][3]));
        }
        mx0 = fmaxf(mx0, __shfl_xor_sync(0xffffffffu, mx0, 1));
        mx0 = fmaxf(mx0, __shfl_xor_sync(0xffffffffu, mx0, 2));
        mx1 = fmaxf(mx1, __shfl_xor_sync(0xffffffffu, mx1, 1));
        mx1 = fmaxf(mx1, __shfl_xor_sync(0xffffffffu, mx1, 2));
        const float m0n = fmaxf(m0, mx0), m1n = fmaxf(m1, mx1);
        const float a0 = __expf(m0 - m0n), a1 = __expf(m1 - m1n);
        m0 = m0n; m1 = m1n;
        l0 *= a0; l1 *= a1;
#pragma unroll
        for (int ni = 0; ni < 8; ni++) {
            o[ni][0] *= a0; o[ni][1] *= a0;
            o[ni][2] *= a1; o[ni][3] *= a1;
        }

        // ---- P = exp(S-m); PV accumulate ----
        float sum0 = 0.f, sum1 = 0.f;
#pragma unroll
        for (int j = 0; j < 4; j++) {
            float p00 = __expf(s[2 * j][0] - m0),     p01 = __expf(s[2 * j][1] - m0);
            float p02 = __expf(s[2 * j][2] - m1),     p03 = __expf(s[2 * j][3] - m1);
            float p10 = __expf(s[2 * j + 1][0] - m0), p11 = __expf(s[2 * j + 1][1] - m0);
            float p12 = __expf(s[2 * j + 1][2] - m1), p13 = __expf(s[2 * j + 1][3] - m1);
            sum0 += p00 + p01 + p10 + p11;
            sum1 += p02 + p03 + p12 + p13;
            bf16 hh0, ll0, hh1, ll1;
            uint32_t ph[4], pl[4];
            split_f(p00, hh0, ll0); split_f(p01, hh1, ll1);
            ph[0] = pack2(hh0, hh1); pl[0] = pack2(ll0, ll1);
            split_f(p02, hh0, ll0); split_f(p03, hh1, ll1);
            ph[1] = pack2(hh0, hh1); pl[1] = pack2(ll0, ll1);
            split_f(p10, hh0, ll0); split_f(p11, hh1, ll1);
            ph[2] = pack2(hh0, hh1); pl[2] = pack2(ll0, ll1);
            split_f(p12, hh0, ll0); split_f(p13, hh1, ll1);
            ph[3] = pack2(hh0, hh1); pl[3] = pack2(ll0, ll1);
#pragma unroll
            for (int p = 0; p < 4; p++) {
                uint32_t off = (uint32_t)((p * 16 + lrB) * FQ_PITCH + (j * 2 + cB) * 16);
                uint32_t tb[4], tl4[4];
                LDX4(tb, sV + off);
                LDX4(tl4, sV + FS_KL + off);
                uint32_t b0h[2] = { tb[0], tb[1] }, b1h[2] = { tb[2], tb[3] };
                uint32_t b0l[2] = { tl4[0], tl4[1] }, b1l[2] = { tl4[2], tl4[3] };
                mma_bf(o[2 * p],     ph, b0h);
                mma_bf(o[2 * p],     pl, b0h);
                mma_bf(o[2 * p],     ph, b0l);
                mma_bf(o[2 * p + 1], ph, b1h);
                mma_bf(o[2 * p + 1], pl, b1h);
                mma_bf(o[2 * p + 1], ph, b1l);
            }
        }
        sum0 += __shfl_xor_sync(0xffffffffu, sum0, 1);
        sum0 += __shfl_xor_sync(0xffffffffu, sum0, 2);
        sum1 += __shfl_xor_sync(0xffffffffu, sum1, 1);
        sum1 += __shfl_xor_sync(0xffffffffu, sum1, 2);
        l0 += sum0; l1 += sum1;

        __syncthreads();
    }

    // ---- epilogue: O/l + AV, split hi/lo -> th/tl ----
    const float i0 = 1.f / l0, i1 = 1.f / l1;
    const int row = qt * 128 + wid * 16 + (lane >> 2);
    const int colb = h * 64 + (lane & 3) * 2;
#pragma unroll
    for (int ni = 0; ni < 8; ni++) {
        const int col = colb + ni * 8;
        const long off0 = ((long)(b * Nn + row)) * Cc + col;
        const long off1 = off0 + (long)8 * Cc;
        float2 av0 = *(const float2*)(av_ + off0);
        float2 av1 = *(const float2*)(av_ + off1);
        float v0 = o[ni][0] * i0 + av0.x;
        float v1 = o[ni][1] * i0 + av0.y;
        float v2 = o[ni][2] * i1 + av1.x;
        float v3 = o[ni][3] * i1 + av1.y;
        bf16 hh, ll, hh2, ll2;
        split_f(v0, hh, ll); split_f(v1, hh2, ll2);
        *(uint32_t*)(th_ + off0) = pack2(hh, hh2);
        *(uint32_t*)(tl_ + off0) = pack2(ll, ll2);
        split_f(v2, hh, ll); split_f(v3, hh2, ll2);
        *(uint32_t*)(th_ + off1) = pack2(hh, hh2);
        *(uint32_t*)(tl_ + off1) = pack2(ll, ll2);
    }
}

// ---------------- elementwise / rearrange kernels ----------------
__global__ __launch_bounds__(256) void split_kernel(const float* __restrict__ in,
                                                    bf16* __restrict__ h, bf16* __restrict__ l, long n4)
{
    long i = (long)blockIdx.x * 256 + threadIdx.x;
    if (i >= n4) return;
    float4 v = ((const float4*)in)[i];
    bf16 h0, l0, h1, l1, h2, l2, h3, l3;
    split_f(v.x, h0, l0); split_f(v.y, h1, l1);
    split_f(v.z, h2, l2); split_f(v.w, h3, l3);
    uint2 uh = { pack2(h0, h1), pack2(h2, h3) };
    uint2 ul = { pack2(l0, l1), pack2(l2, l3) };
    ((uint2*)h)[i] = uh;
    ((uint2*)l)[i] = ul;
}

// Q/K rearrange+split; q scaled by 0.125
__global__ __launch_bounds__(256) void qk_split_kernel(const float* __restrict__ qkv,
    bf16* __restrict__ qh, bf16* __restrict__ ql, bf16* __restrict__ kh, bf16* __restrict__ kl)
{
    long row = blockIdx.y;
    int col = blockIdx.x * 1024 + threadIdx.x * 4;
    if (col >= 1536) return;
    float4 v = *(const float4*)(qkv + row * (3 * Cc) + col);
    int part = col / Cc, rem = col - part * Cc;
    int h = rem >> 6, d = rem & 63;
    long b = row >> 10, n = row & 1023;
    long dst = (((b * Hh + h) * (long)Nn) + n) * Dd + d;
    const float sc = (part == 0) ? 0.125f : 1.0f;
    v.x *= sc; v.y *= sc; v.z *= sc; v.w *= sc;
    bf16 h0, l0, h1, l1, h2, l2, h3, l3;
    split_f(v.x, h0, l0); split_f(v.y, h1, l1);
    split_f(v.z, h2, l2); split_f(v.w, h3, l3);
    uint2 uh = { pack2(h0, h1), pack2(h2, h3) };
    uint2 ul = { pack2(l0, l1), pack2(l2, l3) };
    if (part == 0) { *(uint2*)(qh + dst) = uh; *(uint2*)(ql + dst) = ul; }
    else           { *(uint2*)(kh + dst) = uh; *(uint2*)(kl + dst) = ul; }
}

// V transpose+split: qkv[b*N+n, 1536 + h*64 + d] -> vt[(b*H+h)*64 + d, n]
__global__ __launch_bounds__(256) void v_split_kernel(const float* __restrict__ qkv,
    bf16* __restrict__ vth, bf16* __restrict__ vtl)
{
    __shared__ float s[64][65];
    int bh = blockIdx.y;
    long b = bh / Hh;
    int h = bh % Hh;
    int n0 = blockIdx.x * 64;
    int t = threadIdx.x;
#pragma unroll
    for (int p = 0; p < 4; p++) {
        int n = p * 16 + (t >> 4);
        int d = (t & 15) * 4;
        float4 v = *(const float4*)(qkv + (b * Nn + n0 + n) * (long)(3 * Cc) + 2 * Cc + h * 64 + d);
        s[d + 0][n] = v.x; s[d + 1][n] = v.y; s[d + 2][n] = v.z; s[d + 3][n] = v.w;
    }
    __syncthreads();
#pragma unroll
    for (int p = 0; p < 4; p++) {
        int d = p * 16 + (t >> 4);
        int n = (t & 15) * 4;
        float4 v = { s[d][n], s[d][n + 1], s[d][n + 2], s[d][n + 3] };
        bf16 h0, l0, h1, l1, h2, l2, h3, l3;
        split_f(v.x, h0, l0); split_f(v.y, h1, l1);
        split_f(v.z, h2, l2); split_f(v.w, h3, l3);
        uint2 uh = { pack2(h0, h1), pack2(h2, h3) };
        uint2 ul = { pack2(l0, l1), pack2(l2, l3) };
        long dst = ((long)bh * Dd + d) * Nn + n0 + n;
        *(uint2*)(vth + dst) = uh;
        *(uint2*)(vtl + dst) = ul;
    }
}

// ---------------- launch ----------------
extern "C" void kernel_launch(void* const* d_in, const int* in_sizes, int n_in,
                              void* d_out, int out_size)
{
    const float* x        = (const float*)d_in[0];
    const float* qkv_w    = (const float*)d_in[1];
    const float* qkv_b    = (const float*)d_in[2];
    const float* static_a = (const float*)d_in[3];
    const float* proj_w   = (const float*)d_in[4];
    const float* proj_b   = (const float*)d_in[5];
    float* out = (float*)d_out;

    float *qkvp, *avp;
    bf16 *xh, *xl, *wqh, *wql, *wph, *wpl, *qh, *ql, *kh, *kl, *vth, *vtl, *sah, *sal, *th, *tl;
    cudaGetSymbolAddress((void**)&qkvp, g_qkv);
    cudaGetSymbolAddress((void**)&avp, g_av);
    cudaGetSymbolAddress((void**)&xh, g_xh);   cudaGetSymbolAddress((void**)&xl, g_xl);
    cudaGetSymbolAddress((void**)&wqh, g_wqh); cudaGetSymbolAddress((void**)&wql, g_wql);
    cudaGetSymbolAddress((void**)&wph, g_wph); cudaGetSymbolAddress((void**)&wpl, g_wpl);
    cudaGetSymbolAddress((void**)&qh, g_qh);   cudaGetSymbolAddress((void**)&ql, g_ql);
    cudaGetSymbolAddress((void**)&kh, g_kh);   cudaGetSymbolAddress((void**)&kl, g_kl);
    cudaGetSymbolAddress((void**)&vth, g_vth); cudaGetSymbolAddress((void**)&vtl, g_vtl);
    cudaGetSymbolAddress((void**)&sah, g_sah); cudaGetSymbolAddress((void**)&sal, g_sal);
    cudaGetSymbolAddress((void**)&th, g_th);   cudaGetSymbolAddress((void**)&tl, g_tl);

    const int SM64 = 2 * G_STG;   // 61440
    cudaFuncSetAttribute(gemm_mma, cudaFuncAttributeMaxDynamicSharedMemorySize, SM64);
    cudaFuncSetAttribute(flash_kernel, cudaFuncAttributeMaxDynamicSharedMemorySize, F_SMEM);

    // 0) input splits
    split_kernel<<<(Bb * Nn * Cc / 4 + 255) / 256, 256>>>(x, xh, xl, (long)Bb * Nn * Cc / 4);
    split_kernel<<<(3 * Cc * Cc / 4 + 255) / 256, 256>>>(qkv_w, wqh, wql, (long)3 * Cc * Cc / 4);
    split_kernel<<<(Cc * Cc / 4 + 255) / 256, 256>>>(proj_w, wph, wpl, (long)Cc * Cc / 4);
    split_kernel<<<((long)Hh * Nn * Nn / 4 + 255) / 256, 256>>>(static_a, sah, sal, (long)Hh * Nn * Nn / 4);

    // 1) QKV GEMM -> fp32 qkv
    gemm_mma<<<dim3(3 * Cc / 64, Bb * Nn / 128, 1), 256, SM64>>>(
        xh, xl, Cc, 0, 0,
        wqh, wql, Cc, 0, 0,
        qkvp, 3 * Cc, 0, 0,
        Cc, qkv_b, 1.0f, 1);

    // 2) rearrange + split q(scaled)/k/vT
    qk_split_kernel<<<dim3(2, Bb * Nn), 256>>>(qkvp, qh, ql, kh, kl);
    v_split_kernel<<<dim3(Nn / 64, Bb * Hh), 256>>>(qkvp, vth, vtl);

    // 3) AV = static_a @ V per (h,b) -> fp32 g_av[b,n,h*64+d]
    gemm_mma<<<dim3(1, Nn / 128, Hh * Bb), 256, SM64>>>(
        sah, sal, Nn, (long)Nn * Nn, 0,
        vth, vtl, Nn, (long)Dd * Nn, (long)Hh * Dd * Nn,
        avp, Cc, 64, (long)Nn * Cc,
        Nn, nullptr, 1.0f, Bb);

    // 4) flash: softmax(QK^T)V + AV -> hi/lo bf16 g_th/g_tl [B,N,C]
    flash_kernel<<<dim3(Nn / 128, Bb * Hh), 256, F_SMEM>>>(
        qh, ql, kh, kl, vth, vtl, avp, th, tl);

    // 5) Proj -> out
    gemm_mma<<<dim3(Cc / 64, Bb * Nn / 128, 1), 256, SM64>>>(
        th, tl, Cc, 0, 0,
        wph, wpl, Cc, 0, 0,
        out, Cc, 0, 0,
        Cc, proj_b, 1.0f, 1);
}

// round 6
// speedup vs baseline: 1.0739x; 1.0739x over previous
#include <cuda_runtime.h>
#include <cuda_bf16.h>
#include <cstdint>

// Problem constants
#define Bb 8
#define Nn 1024
#define Cc 768
#define Hh 12
#define Dd 64

typedef __nv_bfloat16 bf16;

// ---------------- scratch (__device__ globals; allocation-free) ----------------
__device__ float g_qkv[(size_t)Bb * Nn * 3 * Cc];      // fp32 qkv
__device__ float g_av [(size_t)Bb * Nn * Cc];          // fp32 A@V

__device__ bf16 g_xh[(size_t)Bb * Nn * Cc], g_xl[(size_t)Bb * Nn * Cc];
__device__ bf16 g_wqh[(size_t)3 * Cc * Cc], g_wql[(size_t)3 * Cc * Cc];
__device__ bf16 g_wph[(size_t)Cc * Cc],     g_wpl[(size_t)Cc * Cc];
__device__ bf16 g_qh [(size_t)Bb * Hh * Nn * Dd], g_ql [(size_t)Bb * Hh * Nn * Dd];
__device__ bf16 g_kh [(size_t)Bb * Hh * Nn * Dd], g_kl [(size_t)Bb * Hh * Nn * Dd];
__device__ bf16 g_vth[(size_t)Bb * Hh * Dd * Nn], g_vtl[(size_t)Bb * Hh * Dd * Nn];
__device__ bf16 g_sah[(size_t)Hh * Nn * Nn], g_sal[(size_t)Hh * Nn * Nn];
__device__ bf16 g_th [(size_t)Bb * Nn * Cc], g_tl [(size_t)Bb * Nn * Cc];

// ---------------- helpers ----------------
__device__ __forceinline__ uint32_t smem_u32(const void* p) {
    uint32_t a;
    asm("{ .reg .u64 t; cvta.to.shared.u64 t, %1; cvt.u32.u64 %0, t; }" : "=r"(a) : "l"(p));
    return a;
}
__device__ __forceinline__ void cpasync16(uint32_t dst, const void* src) {
    asm volatile("cp.async.cg.shared.global [%0], [%1], 16;" :: "r"(dst), "l"(src));
}
#define CP_COMMIT() asm volatile("cp.async.commit_group;" ::: "memory")
#define CP_WAIT1()  asm volatile("cp.async.wait_group 1;" ::: "memory")
#define CP_WAIT0()  asm volatile("cp.async.wait_group 0;" ::: "memory")

#define LDX4(r, a)                                                               \
    asm volatile("ldmatrix.sync.aligned.m8n8.x4.shared.b16 {%0,%1,%2,%3}, [%4];" \
        : "=r"((r)[0]), "=r"((r)[1]), "=r"((r)[2]), "=r"((r)[3]) : "r"(a))

__device__ __forceinline__ void mma_bf(float* c, const uint32_t* a, const uint32_t* b) {
    asm volatile(
        "mma.sync.aligned.m16n8k16.row.col.f32.bf16.bf16.f32 "
        "{%0,%1,%2,%3}, {%4,%5,%6,%7}, {%8,%9}, {%0,%1,%2,%3};"
        : "+f"(c[0]), "+f"(c[1]), "+f"(c[2]), "+f"(c[3])
        : "r"(a[0]), "r"(a[1]), "r"(a[2]), "r"(a[3]), "r"(b[0]), "r"(b[1]));
}

__device__ __forceinline__ void split_f(float v, bf16& h, bf16& l) {
    h = __float2bfloat16(v);
    l = __float2bfloat16(v - __bfloat162float(h));
}
__device__ __forceinline__ uint32_t pack2(bf16 a, bf16 b) {
    __nv_bfloat162 t(a, b);
    return *reinterpret_cast<uint32_t*>(&t);
}

// ---------------- dense MMA GEMM (R4 config: BM=128, BN in {128,64}, BK=32) --------------
template <int BN>
__device__ __forceinline__ void load_stage(
    uint32_t sb, int tid, int row0, int col0, int k0,
    const bf16* __restrict__ Ah, const bf16* __restrict__ Al, int lda,
    const bf16* __restrict__ Bh, const bf16* __restrict__ Bl, int ldb)
{
#pragma unroll
    for (int v = 0; v < 2; v++) {
        int idx = tid + v * 256;
        int r = idx >> 2, ch = idx & 3;
        long go = (long)(row0 + r) * lda + k0 + ch * 8;
        uint32_t d = sb + r * 80 + ch * 16;
        cpasync16(d,         Ah + go);
        cpasync16(d + 10240, Al + go);
    }
#pragma unroll
    for (int v = 0; v < BN / 64; v++) {
        int idx = tid + v * 256;
        int r = idx >> 2, ch = idx & 3;
        long go = (long)(col0 + r) * ldb + k0 + ch * 8;
        uint32_t d = sb + 20480 + r * 80 + ch * 16;
        cpasync16(d,           Bh + go);
        cpasync16(d + BN * 80, Bl + go);
    }
}

template <int BN>
__global__ __launch_bounds__(256) void gemm_mma(
    const bf16* __restrict__ Ah, const bf16* __restrict__ Al, int lda, long sAo, long sAi,
    const bf16* __restrict__ Bh, const bf16* __restrict__ Bl, int ldb, long sBo, long sBi,
    float* __restrict__ C, int ldc, long sCo, long sCi,
    int K, const float* __restrict__ bias, float scale, int hdiv)
{
    constexpr int NT  = BN / 32;
    constexpr int STG = 20480 + BN * 160;

    extern __shared__ char smem[];
    const uint32_t sbase = smem_u32(smem);

    const int tid = threadIdx.x;
    const int wid = tid >> 5, lane = tid & 31;
    const int wr = wid >> 2, wc = wid & 3;
    const int wm0 = wr * 64;
    const int wn0 = wc * (BN / 4);

    const int z = blockIdx.z;
    const int zo = z / hdiv, zi = z - zo * hdiv;
    Ah += (long)zo * sAo + (long)zi * sAi;
    Al += (long)zo * sAo + (long)zi * sAi;
    Bh += (long)zo * sBo + (long)zi * sBi;
    Bl += (long)zo * sBo + (long)zi * sBi;
    const long cofs = (long)zo * sCo + (long)zi * sCi;

    const int row0 = blockIdx.y * 128;
    const int col0 = blockIdx.x * BN;

    const int lrA = (lane & 7) + ((lane >> 3) & 1) * 8;
    const int cA  = lane >> 4;
    const int lrB = (lane & 7) + (lane >> 4) * 8;
    const int cB  = (lane >> 3) & 1;

    float acc[4][NT][4];
#pragma unroll
    for (int mi = 0; mi < 4; mi++)
#pragma unroll
        for (int ni = 0; ni < NT; ni++)
#pragma unroll
            for (int e = 0; e < 4; e++) acc[mi][ni][e] = 0.f;

    const int niter = K >> 5;
    load_stage<BN>(sbase, tid, row0, col0, 0, Ah, Al, lda, Bh, Bl, ldb);
    CP_COMMIT();

    for (int c = 0; c < niter; c++) {
        if (c + 1 < niter) {
            load_stage<BN>(sbase + ((c + 1) & 1) * STG, tid, row0, col0, (c + 1) * 32,
                           Ah, Al, lda, Bh, Bl, ldb);
            CP_COMMIT();
            CP_WAIT1();
        } else {
            CP_WAIT0();
        }
        __syncthreads();

        const uint32_t sb = sbase + (c & 1) * STG;
#pragma unroll
        for (int kk = 0; kk < 2; kk++) {
            uint32_t ah[4][4], al[4][4], bhf[NT][2], blf[NT][2];
#pragma unroll
            for (int mi = 0; mi < 4; mi++) {
                uint32_t off = (uint32_t)((wm0 + mi * 16 + lrA) * 80 + (kk * 2 + cA) * 16);
                LDX4(ah[mi], sb + off);
                LDX4(al[mi], sb + 10240 + off);
            }
#pragma unroll
            for (int pi = 0; pi < NT / 2; pi++) {
                uint32_t off = (uint32_t)((wn0 + pi * 16 + lrB) * 80 + (kk * 2 + cB) * 16);
                uint32_t t[4];
                LDX4(t, sb + 20480 + off);
                bhf[2 * pi][0] = t[0]; bhf[2 * pi][1] = t[1];
                bhf[2 * pi + 1][0] = t[2]; bhf[2 * pi + 1][1] = t[3];
                LDX4(t, sb + 20480 + BN * 80 + off);
                blf[2 * pi][0] = t[0]; blf[2 * pi][1] = t[1];
                blf[2 * pi + 1][0] = t[2]; blf[2 * pi + 1][1] = t[3];
            }
#pragma unroll
            for (int mi = 0; mi < 4; mi++)
#pragma unroll
                for (int ni = 0; ni < NT; ni++) {
                    mma_bf(acc[mi][ni], ah[mi], bhf[ni]);
                    mma_bf(acc[mi][ni], ah[mi], blf[ni]);
                    mma_bf(acc[mi][ni], al[mi], bhf[ni]);
                }
        }
        __syncthreads();
    }

#pragma unroll
    for (int ni = 0; ni < NT; ni++) {
        const int col = col0 + wn0 + ni * 8 + (lane & 3) * 2;
        float b0 = 0.f, b1 = 0.f;
        if (bias) { b0 = bias[col]; b1 = bias[col + 1]; }
#pragma unroll
        for (int mi = 0; mi < 4; mi++) {
            const int r = row0 + wm0 + mi * 16 + (lane >> 2);
            const long off0 = cofs + (long)r * ldc + col;
            const long off1 = off0 + (long)8 * ldc;
            float2 p0 = { acc[mi][ni][0] * scale + b0, acc[mi][ni][1] * scale + b1 };
            float2 p1 = { acc[mi][ni][2] * scale + b0, acc[mi][ni][3] * scale + b1 };
            *(float2*)(C + off0) = p0;
            *(float2*)(C + off1) = p1;
        }
    }
}

// ---------------- flash attention: O = softmax(Q K^T) V  (+ g_av) ----------------
// ktile=64, 2-stage, smem 110592, __launch_bounds__(256,2) -> 2 CTA/SM resident.
#define FQ_PITCH 144
#define F_QL   18432
#define F_S0   36864
#define FS_KL  9216
#define FS_VH  18432
#define F_STG  36864
#define F_SMEM (36864 + 2 * 36864)

__device__ __forceinline__ void flash_load_kv(
    uint32_t dst, int tid, int kt,
    const bf16* __restrict__ Kh, const bf16* __restrict__ Kl,
    const bf16* __restrict__ Vth, const bf16* __restrict__ Vtl)
{
#pragma unroll
    for (int v = 0; v < 2; v++) {
        int idx = tid + v * 256;             // 512: 64 rows x 8 chunks
        int r = idx >> 3, ch = idx & 7;
        uint32_t d = dst + r * FQ_PITCH + ch * 16;
        long src = (long)(kt * 64 + r) * 64 + ch * 8;
        cpasync16(d,         Kh + src);
        cpasync16(d + FS_KL, Kl + src);
    }
#pragma unroll
    for (int v = 0; v < 2; v++) {
        int idx = tid + v * 256;             // 512: 64 d-rows x 8 chunks
        int r = idx >> 3, ch = idx & 7;
        uint32_t d = dst + FS_VH + r * FQ_PITCH + ch * 16;
        long src = (long)r * Nn + kt * 64 + ch * 8;
        cpasync16(d,         Vth + src);
        cpasync16(d + FS_KL, Vtl + src);
    }
}

__global__ __launch_bounds__(256, 2) void flash_kernel(
    const bf16* __restrict__ qh_, const bf16* __restrict__ ql_,
    const bf16* __restrict__ kh_, const bf16* __restrict__ kl_,
    const bf16* __restrict__ vth_, const bf16* __restrict__ vtl_,
    const float* __restrict__ av_,
    bf16* __restrict__ th_, bf16* __restrict__ tl_)
{
    extern __shared__ char smem[];
    const uint32_t sb = smem_u32(smem);
    const int tid = threadIdx.x, wid = tid >> 5, lane = tid & 31;
    const int qt = blockIdx.x, bh = blockIdx.y;
    const int b = bh / Hh, h = bh - b * Hh;

    const bf16* Qh  = qh_  + (long)bh * Nn * Dd + (long)qt * 128 * Dd;
    const bf16* Ql  = ql_  + (long)bh * Nn * Dd + (long)qt * 128 * Dd;
    const bf16* Kh  = kh_  + (long)bh * Nn * Dd;
    const bf16* Kl  = kl_  + (long)bh * Nn * Dd;
    const bf16* Vth = vth_ + (long)bh * Dd * Nn;
    const bf16* Vtl = vtl_ + (long)bh * Dd * Nn;

    const int lrA = (lane & 7) + ((lane >> 3) & 1) * 8;
    const int cA  = lane >> 4;
    const int lrB = (lane & 7) + (lane >> 4) * 8;
    const int cB  = (lane >> 3) & 1;

    // prologue: Q (128 rows x 64) + stage 0
#pragma unroll
    for (int v = 0; v < 4; v++) {
        int idx = tid + v * 256;
        int r = idx >> 3, ch = idx & 7;
        uint32_t d = sb + r * FQ_PITCH + ch * 16;
        long src = (long)r * 64 + ch * 8;
        cpasync16(d,        Qh + src);
        cpasync16(d + F_QL, Ql + src);
    }
    flash_load_kv(sb + F_S0, tid, 0, Kh, Kl, Vth, Vtl);
    CP_COMMIT();

    uint32_t qfh[4][4], qfl[4][4];
    float o[8][4];
#pragma unroll
    for (int ni = 0; ni < 8; ni++)
#pragma unroll
        for (int e = 0; e < 4; e++) o[ni][e] = 0.f;
    float m0 = -1e30f, m1 = -1e30f, l0 = 0.f, l1 = 0.f;

    for (int kt = 0; kt < 16; kt++) {
        if (kt + 1 < 16) {
            flash_load_kv(sb + F_S0 + ((kt + 1) & 1) * F_STG, tid, kt + 1, Kh, Kl, Vth, Vtl);
            CP_COMMIT();
            CP_WAIT1();
        } else {
            CP_WAIT0();
        }
        __syncthreads();

        if (kt == 0) {
#pragma unroll
            for (int kc = 0; kc < 4; kc++) {
                uint32_t off = (uint32_t)((wid * 16 + lrA) * FQ_PITCH + (kc * 2 + cA) * 16);
                LDX4(qfh[kc], sb + off);
                LDX4(qfl[kc], sb + F_QL + off);
            }
        }

        const uint32_t sK = sb + F_S0 + (kt & 1) * F_STG;
        const uint32_t sV = sK + FS_VH;

        // ---- S = Q K^T  (m16 x n64) ----
        float s[8][4];
#pragma unroll
        for (int j = 0; j < 8; j++)
#pragma unroll
            for (int e = 0; e < 4; e++) s[j][e] = 0.f;
#pragma unroll
        for (int p = 0; p < 4; p++) {
#pragma unroll
            for (int kc = 0; kc < 4; kc++) {
                uint32_t off = (uint32_t)((p * 16 + lrB) * FQ_PITCH + (kc * 2 + cB) * 16);
                uint32_t tb[4], tl4[4];
                LDX4(tb, sK + off);
                LDX4(tl4, sK + FS_KL + off);
                uint32_t b0h[2] = { tb[0], tb[1] }, b1h[2] = { tb[2], tb[3] };
                uint32_t b0l[2] = { tl4[0], tl4[1] }, b1l[2] = { tl4[2], tl4[3] };
                mma_bf(s[2 * p],     qfh[kc], b0h);
                mma_bf(s[2 * p],     qfh[kc], b0l);
                mma_bf(s[2 * p],     qfl[kc], b0h);
                mma_bf(s[2 * p + 1], qfh[kc], b1h);
                mma_bf(s[2 * p + 1], qfh[kc], b1l);
                mma_bf(s[2 * p + 1], qfl[kc], b1h);
            }
        }

        // ---- online softmax stats ----
        float mx0 = -1e30f, mx1 = -1e30f;
#pragma unroll
        for (int j = 0; j < 8; j++) {
            mx0 = fmaxf(mx0, fmaxf(s[j][0], s[j][1]));
            mx1 = fmaxf(mx1, fmaxf(s[j][2], s[j][3]));
        }
        mx0 = fmaxf(mx0, __shfl_xor_sync(0xffffffffu, mx0, 1));
        mx0 = fmaxf(mx0, __shfl_xor_sync(0xffffffffu, mx0, 2));
        mx1 = fmaxf(mx1, __shfl_xor_sync(0xffffffffu, mx1, 1));
        mx1 = fmaxf(mx1, __shfl_xor_sync(0xffffffffu, mx1, 2));
        const float m0n = fmaxf(m0, mx0), m1n = fmaxf(m1, mx1);
        const float a0 = __expf(m0 - m0n), a1 = __expf(m1 - m1n);
        m0 = m0n; m1 = m1n;
        l0 *= a0; l1 *= a1;
#pragma unroll
        for (int ni = 0; ni < 8; ni++) {
            o[ni][0] *= a0; o[ni][1] *= a0;
            o[ni][2] *= a1; o[ni][3] *= a1;
        }

        // ---- P = exp(S-m); PV accumulate ----
        float sum0 = 0.f, sum1 = 0.f;
#pragma unroll
        for (int j = 0; j < 4; j++) {
            float p00 = __expf(s[2 * j][0] - m0),     p01 = __expf(s[2 * j][1] - m0);
            float p02 = __expf(s[2 * j][2] - m1),     p03 = __expf(s[2 * j][3] - m1);
            float p10 = __expf(s[2 * j + 1][0] - m0), p11 = __expf(s[2 * j + 1][1] - m0);
            float p12 = __expf(s[2 * j + 1][2] - m1), p13 = __expf(s[2 * j + 1][3] - m1);
            sum0 += p00 + p01 + p10 + p11;
            sum1 += p02 + p03 + p12 + p13;
            bf16 hh0, ll0, hh1, ll1;
            uint32_t ph[4], pl[4];
            split_f(p00, hh0, ll0); split_f(p01, hh1, ll1);
            ph[0] = pack2(hh0, hh1); pl[0] = pack2(ll0, ll1);
            split_f(p02, hh0, ll0); split_f(p03, hh1, ll1);
            ph[1] = pack2(hh0, hh1); pl[1] = pack2(ll0, ll1);
            split_f(p10, hh0, ll0); split_f(p11, hh1, ll1);
            ph[2] = pack2(hh0, hh1); pl[2] = pack2(ll0, ll1);
            split_f(p12, hh0, ll0); split_f(p13, hh1, ll1);
            ph[3] = pack2(hh0, hh1); pl[3] = pack2(ll0, ll1);
#pragma unroll
            for (int p = 0; p < 4; p++) {
                uint32_t off = (uint32_t)((p * 16 + lrB) * FQ_PITCH + (j * 2 + cB) * 16);
                uint32_t tb[4], tl4[4];
                LDX4(tb, sV + off);
                LDX4(tl4, sV + FS_KL + off);
                uint32_t b0h[2] = { tb[0], tb[1] }, b1h[2] = { tb[2], tb[3] };
                uint32_t b0l[2] = { tl4[0], tl4[1] }, b1l[2] = { tl4[2], tl4[3] };
                mma_bf(o[2 * p],     ph, b0h);
                mma_bf(o[2 * p],     pl, b0h);
                mma_bf(o[2 * p],     ph, b0l);
                mma_bf(o[2 * p + 1], ph, b1h);
                mma_bf(o[2 * p + 1], pl, b1h);
                mma_bf(o[2 * p + 1], ph, b1l);
            }
        }
        sum0 += __shfl_xor_sync(0xffffffffu, sum0, 1);
        sum0 += __shfl_xor_sync(0xffffffffu, sum0, 2);
        sum1 += __shfl_xor_sync(0xffffffffu, sum1, 1);
        sum1 += __shfl_xor_sync(0xffffffffu, sum1, 2);
        l0 += sum0; l1 += sum1;

        __syncthreads();
    }

    // ---- epilogue: O/l + AV, split hi/lo -> th/tl ----
    const float i0 = 1.f / l0, i1 = 1.f / l1;
    const int row = qt * 128 + wid * 16 + (lane >> 2);
    const int colb = h * 64 + (lane & 3) * 2;
#pragma unroll
    for (int ni = 0; ni < 8; ni++) {
        const int col = colb + ni * 8;
        const long off0 = ((long)(b * Nn + row)) * Cc + col;
        const long off1 = off0 + (long)8 * Cc;
        float2 av0 = *(const float2*)(av_ + off0);
        float2 av1 = *(const float2*)(av_ + off1);
        float v0 = o[ni][0] * i0 + av0.x;
        float v1 = o[ni][1] * i0 + av0.y;
        float v2 = o[ni][2] * i1 + av1.x;
        float v3 = o[ni][3] * i1 + av1.y;
        bf16 hh, ll, hh2, ll2;
        split_f(v0, hh, ll); split_f(v1, hh2, ll2);
        *(uint32_t*)(th_ + off0) = pack2(hh, hh2);
        *(uint32_t*)(tl_ + off0) = pack2(ll, ll2);
        split_f(v2, hh, ll); split_f(v3, hh2, ll2);
        *(uint32_t*)(th_ + off1) = pack2(hh, hh2);
        *(uint32_t*)(tl_ + off1) = pack2(ll, ll2);
    }
}

// ---------------- elementwise / rearrange kernels ----------------
__global__ __launch_bounds__(256) void split_kernel(const float* __restrict__ in,
                                                    bf16* __restrict__ h, bf16* __restrict__ l, long n4)
{
    long i = (long)blockIdx.x * 256 + threadIdx.x;
    if (i >= n4) return;
    float4 v = ((const float4*)in)[i];
    bf16 h0, l0, h1, l1, h2, l2, h3, l3;
    split_f(v.x, h0, l0); split_f(v.y, h1, l1);
    split_f(v.z, h2, l2); split_f(v.w, h3, l3);
    uint2 uh = { pack2(h0, h1), pack2(h2, h3) };
    uint2 ul = { pack2(l0, l1), pack2(l2, l3) };
    ((uint2*)h)[i] = uh;
    ((uint2*)l)[i] = ul;
}

// Q/K rearrange+split; q scaled by 0.125
__global__ __launch_bounds__(256) void qk_split_kernel(const float* __restrict__ qkv,
    bf16* __restrict__ qh, bf16* __restrict__ ql, bf16* __restrict__ kh, bf16* __restrict__ kl)
{
    long row = blockIdx.y;
    int col = blockIdx.x * 1024 + threadIdx.x * 4;
    if (col >= 1536) return;
    float4 v = *(const float4*)(qkv + row * (3 * Cc) + col);
    int part = col / Cc, rem = col - part * Cc;
    int h = rem >> 6, d = rem & 63;
    long b = row >> 10, n = row & 1023;
    long dst = (((b * Hh + h) * (long)Nn) + n) * Dd + d;
    const float sc = (part == 0) ? 0.125f : 1.0f;
    v.x *= sc; v.y *= sc; v.z *= sc; v.w *= sc;
    bf16 h0, l0, h1, l1, h2, l2, h3, l3;
    split_f(v.x, h0, l0); split_f(v.y, h1, l1);
    split_f(v.z, h2, l2); split_f(v.w, h3, l3);
    uint2 uh = { pack2(h0, h1), pack2(h2, h3) };
    uint2 ul = { pack2(l0, l1), pack2(l2, l3) };
    if (part == 0) { *(uint2*)(qh + dst) = uh; *(uint2*)(ql + dst) = ul; }
    else           { *(uint2*)(kh + dst) = uh; *(uint2*)(kl + dst) = ul; }
}

// V transpose+split
__global__ __launch_bounds__(256) void v_split_kernel(const float* __restrict__ qkv,
    bf16* __restrict__ vth, bf16* __restrict__ vtl)
{
    __shared__ float s[64][65];
    int bh = blockIdx.y;
    long b = bh / Hh;
    int h = bh % Hh;
    int n0 = blockIdx.x * 64;
    int t = threadIdx.x;
#pragma unroll
    for (int p = 0; p < 4; p++) {
        int n = p * 16 + (t >> 4);
        int d = (t & 15) * 4;
        float4 v = *(const float4*)(qkv + (b * Nn + n0 + n) * (long)(3 * Cc) + 2 * Cc + h * 64 + d);
        s[d + 0][n] = v.x; s[d + 1][n] = v.y; s[d + 2][n] = v.z; s[d + 3][n] = v.w;
    }
    __syncthreads();
#pragma unroll
    for (int p = 0; p < 4; p++) {
        int d = p * 16 + (t >> 4);
        int n = (t & 15) * 4;
        float4 v = { s[d][n], s[d][n + 1], s[d][n + 2], s[d][n + 3] };
        bf16 h0, l0, h1, l1, h2, l2, h3, l3;
        split_f(v.x, h0, l0); split_f(v.y, h1, l1);
        split_f(v.z, h2, l2); split_f(v.w, h3, l3);
        uint2 uh = { pack2(h0, h1), pack2(h2, h3) };
        uint2 ul = { pack2(l0, l1), pack2(l2, l3) };
        long dst = ((long)bh * Dd + d) * Nn + n0 + n;
        *(uint2*)(vth + dst) = uh;
        *(uint2*)(vtl + dst) = ul;
    }
}

// ---------------- launch ----------------
extern "C" void kernel_launch(void* const* d_in, const int* in_sizes, int n_in,
                              void* d_out, int out_size)
{
    const float* x        = (const float*)d_in[0];
    const float* qkv_w    = (const float*)d_in[1];
    const float* qkv_b    = (const float*)d_in[2];
    const float* static_a = (const float*)d_in[3];
    const float* proj_w   = (const float*)d_in[4];
    const float* proj_b   = (const float*)d_in[5];
    float* out = (float*)d_out;

    float *qkvp, *avp;
    bf16 *xh, *xl, *wqh, *wql, *wph, *wpl, *qh, *ql, *kh, *kl, *vth, *vtl, *sah, *sal, *th, *tl;
    cudaGetSymbolAddress((void**)&qkvp, g_qkv);
    cudaGetSymbolAddress((void**)&avp, g_av);
    cudaGetSymbolAddress((void**)&xh, g_xh);   cudaGetSymbolAddress((void**)&xl, g_xl);
    cudaGetSymbolAddress((void**)&wqh, g_wqh); cudaGetSymbolAddress((void**)&wql, g_wql);
    cudaGetSymbolAddress((void**)&wph, g_wph); cudaGetSymbolAddress((void**)&wpl, g_wpl);
    cudaGetSymbolAddress((void**)&qh, g_qh);   cudaGetSymbolAddress((void**)&ql, g_ql);
    cudaGetSymbolAddress((void**)&kh, g_kh);   cudaGetSymbolAddress((void**)&kl, g_kl);
    cudaGetSymbolAddress((void**)&vth, g_vth); cudaGetSymbolAddress((void**)&vtl, g_vtl);
    cudaGetSymbolAddress((void**)&sah, g_sah); cudaGetSymbolAddress((void**)&sal, g_sal);
    cudaGetSymbolAddress((void**)&th, g_th);   cudaGetSymbolAddress((void**)&tl, g_tl);

    const int SM128 = 2 * (20480 + 128 * 160);   // 81920
    const int SM64  = 2 * (20480 + 64 * 160);    // 61440
    cudaFuncSetAttribute(gemm_mma<128>, cudaFuncAttributeMaxDynamicSharedMemorySize, SM128);
    cudaFuncSetAttribute(gemm_mma<64>,  cudaFuncAttributeMaxDynamicSharedMemorySize, SM64);
    cudaFuncSetAttribute(flash_kernel, cudaFuncAttributeMaxDynamicSharedMemorySize, F_SMEM);

    // 0) input splits
    split_kernel<<<(Bb * Nn * Cc / 4 + 255) / 256, 256>>>(x, xh, xl, (long)Bb * Nn * Cc / 4);
    split_kernel<<<(3 * Cc * Cc / 4 + 255) / 256, 256>>>(qkv_w, wqh, wql, (long)3 * Cc * Cc / 4);
    split_kernel<<<(Cc * Cc / 4 + 255) / 256, 256>>>(proj_w, wph, wpl, (long)Cc * Cc / 4);
    split_kernel<<<((long)Hh * Nn * Nn / 4 + 255) / 256, 256>>>(static_a, sah, sal, (long)Hh * Nn * Nn / 4);

    // 1) QKV GEMM -> fp32 qkv
    gemm_mma<128><<<dim3(3 * Cc / 128, Bb * Nn / 128, 1), 256, SM128>>>(
        xh, xl, Cc, 0, 0,
        wqh, wql, Cc, 0, 0,
        qkvp, 3 * Cc, 0, 0,
        Cc, qkv_b, 1.0f, 1);

    // 2) rearrange + split q(scaled)/k/vT
    qk_split_kernel<<<dim3(2, Bb * Nn), 256>>>(qkvp, qh, ql, kh, kl);
    v_split_kernel<<<dim3(Nn / 64, Bb * Hh), 256>>>(qkvp, vth, vtl);

    // 3) AV = static_a @ V per (h,b) -> fp32 g_av[b,n,h*64+d]
    gemm_mma<64><<<dim3(1, Nn / 128, Hh * Bb), 256, SM64>>>(
        sah, sal, Nn, (long)Nn * Nn, 0,
        vth, vtl, Nn, (long)Dd * Nn, (long)Hh * Dd * Nn,
        avp, Cc, 64, (long)Nn * Cc,
        Nn, nullptr, 1.0f, Bb);

    // 4) flash: softmax(QK^T)V + AV -> hi/lo bf16 g_th/g_tl [B,N,C]
    flash_kernel<<<dim3(Nn / 128, Bb * Hh), 256, F_SMEM>>>(
        qh, ql, kh, kl, vth, vtl, avp, th, tl);

    // 5) Proj -> out
    gemm_mma<128><<<dim3(Cc / 128, Bb * Nn / 128, 1), 256, SM128>>>(
        th, tl, Cc, 0, 0,
        wph, wpl, Cc, 0, 0,
        out, Cc, 0, 0,
        Cc, proj_b, 1.0f, 1);
}